// round 1
// baseline (speedup 1.0000x reference)
#include <cuda_runtime.h>
#include <cuda_bf16.h>
#include <math.h>

// ---------------- problem constants ----------------
#define L_   6
#define D_   768
#define NH_  12
#define DH_  64
#define T_   512
#define B_   16
#define BT_  (B_ * T_)       // 8192
#define D3_  (3 * D_)        // 2304
#define D4_  (4 * D_)        // 3072

// ---------------- scratch (static device globals; no allocs allowed) ----------------
__device__ float g_x  [BT_ * D_];    // residual stream
__device__ float g_xn [BT_ * D_];    // layernorm output
__device__ float g_qkv[BT_ * D3_];   // qkv projection
__device__ float g_y  [BT_ * D_];    // attention output
__device__ float g_h  [BT_ * D4_];   // mlp hidden
__device__ float g_dm [B_ * D_];     // deck-mean + opp-deck-mean
__device__ char  g_mask[B_ * T_];
__device__ int   g_lastidx[B_];

// ---------------- small helpers ----------------
__device__ __forceinline__ float gelu_exact(float v) {
    return 0.5f * v * (1.0f + erff(v * 0.70710678118654752440f));
}

// ---------------- mask + last_idx ----------------
__global__ void mask_kernel(const int* __restrict__ cards,
                            char* __restrict__ mask, int* __restrict__ lastidx) {
    int b = blockIdx.x;
    int t = threadIdx.x;                       // 512 threads
    bool valid = cards[b * T_ + t] != 0;
    bool any   = __syncthreads_or(valid);
    bool m = valid || (t == 0 && !any);
    mask[b * T_ + t] = m ? 1 : 0;
    int cnt = __syncthreads_count(m);
    if (t == 0) lastidx[b] = (cnt - 1) > 0 ? (cnt - 1) : 0;
}

// ---------------- deck means (sum of both means) ----------------
__global__ void deckmean_kernel(const int* __restrict__ deck, const int* __restrict__ opp,
                                const float* __restrict__ tok, float* __restrict__ dm) {
    int b = blockIdx.x;
    int d = threadIdx.x;                       // 768 threads
    float s = 0.f;
    #pragma unroll
    for (int i = 0; i < 8; i++) {
        s += tok[(size_t)deck[b * 8 + i] * D_ + d];
        s += tok[(size_t)opp [b * 8 + i] * D_ + d];
    }
    dm[b * D_ + d] = s * 0.125f;
}

// ---------------- embedding sum ----------------
__global__ void embed_kernel(const int* __restrict__ cards, const int* __restrict__ players,
                             const float* __restrict__ tok, const float* __restrict__ pemb,
                             const float* __restrict__ pos, const float* __restrict__ dm,
                             float* __restrict__ x) {
    int bt = blockIdx.x;                       // 8192 blocks
    int b = bt >> 9;
    int t = bt & 511;
    int card = cards[bt];
    int pl = players[bt]; pl = pl < 0 ? 0 : (pl > 1 ? 1 : pl);
    const float* tr = tok  + (size_t)card * D_;
    const float* pr = pemb + (size_t)pl * D_;
    const float* qr = pos  + (size_t)t  * D_;
    const float* mr = dm   + (size_t)b  * D_;
    float* xr = x + (size_t)bt * D_;
    for (int d = threadIdx.x; d < D_; d += 256)
        xr[d] = tr[d] + pr[d] + mr[d] + qr[d];
}

// ---------------- layernorm (one row / block, 256 threads, 3 elems/thread) ----------------
__global__ void ln_kernel(const float* __restrict__ x, const float* __restrict__ g,
                          const float* __restrict__ be, float* __restrict__ o) {
    __shared__ float sh1[8], sh2[8];
    int r = blockIdx.x;
    size_t base = (size_t)r * D_;
    int t = threadIdx.x;
    float v0 = x[base + t], v1 = x[base + t + 256], v2 = x[base + t + 512];
    float s = v0 + v1 + v2;
    float q = v0 * v0 + v1 * v1 + v2 * v2;
    #pragma unroll
    for (int o2 = 16; o2; o2 >>= 1) {
        s += __shfl_xor_sync(0xffffffffu, s, o2);
        q += __shfl_xor_sync(0xffffffffu, q, o2);
    }
    if ((t & 31) == 0) { sh1[t >> 5] = s; sh2[t >> 5] = q; }
    __syncthreads();
    s = sh1[t & 7]; q = sh2[t & 7];
    #pragma unroll
    for (int o2 = 4; o2; o2 >>= 1) {
        s += __shfl_xor_sync(0xffffffffu, s, o2);
        q += __shfl_xor_sync(0xffffffffu, q, o2);
    }
    float mean = s * (1.0f / D_);
    float var  = q * (1.0f / D_) - mean * mean;
    float rstd = rsqrtf(var + 1e-5f);
    o[base + t]       = (v0 - mean) * rstd * g[t]       + be[t];
    o[base + t + 256] = (v1 - mean) * rstd * g[t + 256] + be[t + 256];
    o[base + t + 512] = (v2 - mean) * rstd * g[t + 512] + be[t + 512];
}

// ---------------- SGEMM: C = epi(A[MxK] @ W[KxN] + bias) (+res) ----------------
// BM=128, BN=64, BK=16, 256 threads, 8x4 micro-tile per thread.
// EPI: 0 = bias, 1 = bias+gelu, 2 = bias+residual
template<int EPI>
__global__ __launch_bounds__(256)
void gemm_kernel(const float* __restrict__ A, const float* __restrict__ W,
                 const float* __restrict__ bias, const float* __restrict__ res,
                 float* __restrict__ C, int M, int N, int K) {
    __shared__ float As[16][128];   // [k][m]
    __shared__ float Ws[16][64];    // [k][n]
    int bm = blockIdx.y * 128;
    int bn = blockIdx.x * 64;
    int tid = threadIdx.x;
    int ty = tid >> 4, tx = tid & 15;
    int row0 = ty * 8, col0 = tx * 4;
    float acc[8][4];
    #pragma unroll
    for (int i = 0; i < 8; i++)
        #pragma unroll
        for (int j = 0; j < 4; j++) acc[i][j] = 0.f;

    int ar = (tid * 8) >> 4;          // A tile row (0..127)
    int ac = (tid * 8) & 15;          // A tile col (0 or 8)
    int wr = (tid * 4) >> 6;          // W tile row (0..15)
    int wc = (tid * 4) & 63;          // W tile col

    for (int k0 = 0; k0 < K; k0 += 16) {
        const float* ga = A + (size_t)(bm + ar) * K + k0 + ac;
        float4 a0 = *(const float4*)ga;
        float4 a1 = *(const float4*)(ga + 4);
        As[ac + 0][ar] = a0.x; As[ac + 1][ar] = a0.y;
        As[ac + 2][ar] = a0.z; As[ac + 3][ar] = a0.w;
        As[ac + 4][ar] = a1.x; As[ac + 5][ar] = a1.y;
        As[ac + 6][ar] = a1.z; As[ac + 7][ar] = a1.w;
        *(float4*)&Ws[wr][wc] = *(const float4*)(W + (size_t)(k0 + wr) * N + bn + wc);
        __syncthreads();
        #pragma unroll
        for (int kk = 0; kk < 16; kk++) {
            float a[8], bb[4];
            *(float4*)&a[0] = *(const float4*)&As[kk][row0];
            *(float4*)&a[4] = *(const float4*)&As[kk][row0 + 4];
            *(float4*)&bb[0] = *(const float4*)&Ws[kk][col0];
            #pragma unroll
            for (int ii = 0; ii < 8; ii++)
                #pragma unroll
                for (int jj = 0; jj < 4; jj++)
                    acc[ii][jj] += a[ii] * bb[jj];
        }
        __syncthreads();
    }

    #pragma unroll
    for (int ii = 0; ii < 8; ii++) {
        size_t m = (size_t)(bm + row0 + ii);
        #pragma unroll
        for (int jj = 0; jj < 4; jj++) {
            int n = bn + col0 + jj;
            float v = acc[ii][jj] + bias[n];
            if (EPI == 1) v = gelu_exact(v);
            if (EPI == 2) v += res[m * N + n];
            C[m * N + n] = v;
        }
    }
}

// ---------------- flash attention (fp32), 64 queries x 32 keys tiles ----------------
__global__ __launch_bounds__(256)
void attn_kernel(const float* __restrict__ qkv, const char* __restrict__ mask,
                 float* __restrict__ out) {
    // grid: (T/64, NH, B)
    int qt = blockIdx.x, h = blockIdx.y, b = blockIdx.z;
    __shared__ float Qs[64][64];     // [i][k]
    __shared__ float Kst[64][32];    // [k][j]
    __shared__ float Vs[32][64];     // [j][c]
    __shared__ float Ps[64][32];     // [i][j]
    __shared__ char  Ms[32];

    int tid = threadIdx.x;
    int i  = tid >> 2;               // query row within tile
    int jq = tid & 3;                // quad index
    int c0 = jq * 16;                // output column base
    int gq = qt * 64 + i;            // global query index
    const float scale = 0.125f;      // 1/sqrt(64)

    // load Q tile
    {
        int idx = tid * 16;
        int row = idx >> 6;
        int cc = idx & 63;
        const float* g = qkv + ((size_t)(b * T_ + qt * 64 + row)) * D3_ + h * DH_ + cc;
        #pragma unroll
        for (int u = 0; u < 4; u++)
            *(float4*)&Qs[row][cc + u * 4] = *(const float4*)(g + u * 4);
    }

    float O[16];
    #pragma unroll
    for (int cc = 0; cc < 16; cc++) O[cc] = 0.f;
    float m_prev = -INFINITY, l = 0.f;

    int ktmax = (qt + 1) * 2;
    for (int kt = 0; kt < ktmax; kt++) {
        __syncthreads();
        // load K (transposed) and V tiles
        {
            int j  = tid >> 3;               // 0..31
            int d0 = (tid & 7) * 8;          // 0..56
            const float* gk = qkv + ((size_t)(b * T_ + kt * 32 + j)) * D3_ + D_  + h * DH_ + d0;
            const float* gv = qkv + ((size_t)(b * T_ + kt * 32 + j)) * D3_ + 2 * D_ + h * DH_ + d0;
            float4 k0v = *(const float4*)gk;
            float4 k1v = *(const float4*)(gk + 4);
            Kst[d0 + 0][j] = k0v.x; Kst[d0 + 1][j] = k0v.y;
            Kst[d0 + 2][j] = k0v.z; Kst[d0 + 3][j] = k0v.w;
            Kst[d0 + 4][j] = k1v.x; Kst[d0 + 5][j] = k1v.y;
            Kst[d0 + 6][j] = k1v.z; Kst[d0 + 7][j] = k1v.w;
            *(float4*)&Vs[j][d0]     = *(const float4*)gv;
            *(float4*)&Vs[j][d0 + 4] = *(const float4*)(gv + 4);
            if (tid < 32) Ms[tid] = mask[b * T_ + kt * 32 + tid];
        }
        __syncthreads();

        // S = Q K^T for 8 keys per thread
        float s[8];
        #pragma unroll
        for (int jj = 0; jj < 8; jj++) s[jj] = 0.f;
        #pragma unroll
        for (int k = 0; k < 64; k++) {
            float qv = Qs[i][k];
            float4 ka = *(const float4*)&Kst[k][jq * 8];
            float4 kb = *(const float4*)&Kst[k][jq * 8 + 4];
            s[0] += qv * ka.x; s[1] += qv * ka.y; s[2] += qv * ka.z; s[3] += qv * ka.w;
            s[4] += qv * kb.x; s[5] += qv * kb.y; s[6] += qv * kb.z; s[7] += qv * kb.w;
        }
        // mask + scale
        float mt = -INFINITY;
        #pragma unroll
        for (int jj = 0; jj < 8; jj++) {
            int gk = kt * 32 + jq * 8 + jj;
            bool ok = (gk <= gq) && (Ms[jq * 8 + jj] != 0);
            s[jj] = ok ? s[jj] * scale : -INFINITY;
            mt = fmaxf(mt, s[jj]);
        }
        // quad max
        mt = fmaxf(mt, __shfl_xor_sync(0xffffffffu, mt, 1));
        mt = fmaxf(mt, __shfl_xor_sync(0xffffffffu, mt, 2));
        float m_new = fmaxf(m_prev, mt);
        float alpha, psum = 0.f;
        float p[8];
        if (m_new == -INFINITY) {
            alpha = 1.0f;
            #pragma unroll
            for (int jj = 0; jj < 8; jj++) p[jj] = 0.f;
        } else {
            alpha = expf(m_prev - m_new);      // expf(-inf) = 0
            #pragma unroll
            for (int jj = 0; jj < 8; jj++) {
                p[jj] = expf(s[jj] - m_new);
                psum += p[jj];
            }
        }
        psum += __shfl_xor_sync(0xffffffffu, psum, 1);
        psum += __shfl_xor_sync(0xffffffffu, psum, 2);
        l = l * alpha + psum;
        m_prev = m_new;
        #pragma unroll
        for (int cc = 0; cc < 16; cc++) O[cc] *= alpha;
        #pragma unroll
        for (int jj = 0; jj < 8; jj++) Ps[i][jq * 8 + jj] = p[jj];
        __syncthreads();

        // O += P @ V
        #pragma unroll 8
        for (int j = 0; j < 32; j++) {
            float pv = Ps[i][j];
            float4 v0 = *(const float4*)&Vs[j][c0];
            float4 v1 = *(const float4*)&Vs[j][c0 + 4];
            float4 v2 = *(const float4*)&Vs[j][c0 + 8];
            float4 v3 = *(const float4*)&Vs[j][c0 + 12];
            O[0]  += pv * v0.x; O[1]  += pv * v0.y; O[2]  += pv * v0.z; O[3]  += pv * v0.w;
            O[4]  += pv * v1.x; O[5]  += pv * v1.y; O[6]  += pv * v1.z; O[7]  += pv * v1.w;
            O[8]  += pv * v2.x; O[9]  += pv * v2.y; O[10] += pv * v2.z; O[11] += pv * v2.w;
            O[12] += pv * v3.x; O[13] += pv * v3.y; O[14] += pv * v3.z; O[15] += pv * v3.w;
        }
    }

    float rl = (l > 0.f) ? (1.0f / l) : 0.f;
    float* op = out + ((size_t)(b * T_ + qt * 64 + i)) * D_ + h * DH_ + c0;
    #pragma unroll
    for (int cc = 0; cc < 16; cc++) op[cc] = O[cc] * rl;
}

// ---------------- head: out[b][a] = dot(xn[b, last_idx], head_w[:,a]) + head_b ----------------
__global__ void head_kernel(const float* __restrict__ xn, const int* __restrict__ lastidx,
                            const float* __restrict__ hw, const float* __restrict__ hb,
                            float* __restrict__ out) {
    int b = blockIdx.x;
    int w = threadIdx.x >> 5;    // 0..8
    int lane = threadIdx.x & 31;
    const float* h = xn + ((size_t)(b * T_ + lastidx[b])) * D_;
    float s = 0.f;
    for (int d = lane; d < D_; d += 32) s += h[d] * hw[d * 9 + w];
    #pragma unroll
    for (int o = 16; o; o >>= 1) s += __shfl_down_sync(0xffffffffu, s, o);
    if (lane == 0) out[b * 9 + w] = s + hb[w];
}

// ---------------- orchestration ----------------
extern "C" void kernel_launch(void* const* d_in, const int* in_sizes, int n_in,
                              void* d_out, int out_size) {
    const int*   cards   = (const int*)  d_in[0];
    const int*   players = (const int*)  d_in[1];
    const int*   deck    = (const int*)  d_in[2];
    const int*   opp     = (const int*)  d_in[3];
    const float* tok     = (const float*)d_in[4];
    const float* pemb    = (const float*)d_in[5];
    const float* pos     = (const float*)d_in[6];
    // d_in[7] = x_emb (row 18 is exactly zero -> no contribution)
    // d_in[8] = y_emb (row 32 is exactly zero -> no contribution)
    const float* ln1s = (const float*)d_in[9];
    const float* ln1b = (const float*)d_in[10];
    const float* qkvw = (const float*)d_in[11];
    const float* qkvb = (const float*)d_in[12];
    const float* projw = (const float*)d_in[13];
    const float* projb = (const float*)d_in[14];
    const float* ln2s = (const float*)d_in[15];
    const float* ln2b = (const float*)d_in[16];
    const float* fc1w = (const float*)d_in[17];
    const float* fc1b = (const float*)d_in[18];
    const float* fc2w = (const float*)d_in[19];
    const float* fc2b = (const float*)d_in[20];
    const float* lnfs = (const float*)d_in[21];
    const float* lnfb = (const float*)d_in[22];
    const float* headw = (const float*)d_in[23];
    const float* headb = (const float*)d_in[24];

    float *x, *xn, *qkv, *y, *hbuf, *dm;
    char* mask; int* lastidx;
    cudaGetSymbolAddress((void**)&x,    g_x);
    cudaGetSymbolAddress((void**)&xn,   g_xn);
    cudaGetSymbolAddress((void**)&qkv,  g_qkv);
    cudaGetSymbolAddress((void**)&y,    g_y);
    cudaGetSymbolAddress((void**)&hbuf, g_h);
    cudaGetSymbolAddress((void**)&dm,   g_dm);
    cudaGetSymbolAddress((void**)&mask, g_mask);
    cudaGetSymbolAddress((void**)&lastidx, g_lastidx);

    mask_kernel<<<B_, T_>>>(cards, mask, lastidx);
    deckmean_kernel<<<B_, D_>>>(deck, opp, tok, dm);
    embed_kernel<<<BT_, 256>>>(cards, players, tok, pemb, pos, dm, x);

    for (int i = 0; i < L_; i++) {
        ln_kernel<<<BT_, 256>>>(x, ln1s + i * D_, ln1b + i * D_, xn);
        gemm_kernel<0><<<dim3(D3_ / 64, BT_ / 128), 256>>>(
            xn, qkvw + (size_t)i * D_ * D3_, qkvb + i * D3_, nullptr, qkv, BT_, D3_, D_);
        attn_kernel<<<dim3(T_ / 64, NH_, B_), 256>>>(qkv, mask, y);
        gemm_kernel<2><<<dim3(D_ / 64, BT_ / 128), 256>>>(
            y, projw + (size_t)i * D_ * D_, projb + i * D_, x, x, BT_, D_, D_);
        ln_kernel<<<BT_, 256>>>(x, ln2s + i * D_, ln2b + i * D_, xn);
        gemm_kernel<1><<<dim3(D4_ / 64, BT_ / 128), 256>>>(
            xn, fc1w + (size_t)i * D_ * D4_, fc1b + i * D4_, nullptr, hbuf, BT_, D4_, D_);
        gemm_kernel<2><<<dim3(D_ / 64, BT_ / 128), 256>>>(
            hbuf, fc2w + (size_t)i * D4_ * D_, fc2b + i * D_, x, x, BT_, D_, D4_);
    }

    ln_kernel<<<BT_, 256>>>(x, lnfs, lnfb, xn);
    head_kernel<<<B_, 288>>>(xn, lastidx, headw, headb, (float*)d_out);
}

// round 3
// speedup vs baseline: 1.7051x; 1.7051x over previous
#include <cuda_runtime.h>
#include <cuda_bf16.h>
#include <math.h>
#include <stdint.h>

typedef __nv_bfloat16 bf16;

// ---------------- problem constants ----------------
#define L_   6
#define D_   768
#define NH_  12
#define DH_  64
#define T_   512
#define B_   16
#define BT_  (B_ * T_)       // 8192
#define D3_  (3 * D_)        // 2304
#define D4_  (4 * D_)        // 3072

// ---------------- scratch (static device globals; no allocs allowed) ----------------
__device__ __align__(128) float g_x  [BT_ * D_];    // residual stream (fp32)
__device__ __align__(128) float g_xn [BT_ * D_];    // final LN output (fp32)
__device__ __align__(128) float g_qkv[BT_ * D3_];   // qkv projection (fp32)
__device__ __align__(128) bf16  g_xh [BT_ * D_];    // LN out hi
__device__ __align__(128) bf16  g_xl [BT_ * D_];    // LN out lo
__device__ __align__(128) bf16  g_yh [BT_ * D_];    // attn out hi
__device__ __align__(128) bf16  g_yl [BT_ * D_];
__device__ __align__(128) bf16  g_hh [BT_ * D4_];   // mlp hidden hi
__device__ __align__(128) bf16  g_hl [BT_ * D4_];
__device__ __align__(128) float g_dm [B_ * D_];
__device__ char  g_mask[B_ * T_];
__device__ int   g_lastidx[B_];

// transposed+split weights: [N, K] bf16 hi/lo
__device__ __align__(128) bf16 g_qkvT_h[L_ * D3_ * D_];
__device__ __align__(128) bf16 g_qkvT_l[L_ * D3_ * D_];
__device__ __align__(128) bf16 g_projT_h[L_ * D_ * D_];
__device__ __align__(128) bf16 g_projT_l[L_ * D_ * D_];
__device__ __align__(128) bf16 g_fc1T_h[L_ * D4_ * D_];
__device__ __align__(128) bf16 g_fc1T_l[L_ * D4_ * D_];
__device__ __align__(128) bf16 g_fc2T_h[L_ * D_ * D4_];
__device__ __align__(128) bf16 g_fc2T_l[L_ * D_ * D4_];

// ---------------- PTX helpers (family-portable only: cp.async, ldmatrix, mma.sync) ----
__device__ __forceinline__ uint32_t smem_u32(const void* p) {
    uint32_t a;
    asm("{ .reg .u64 t; cvta.to.shared.u64 t, %1; cvt.u32.u64 %0, t; }" : "=r"(a) : "l"(p));
    return a;
}
__device__ __forceinline__ void cp16(uint32_t s, const void* g) {
    asm volatile("cp.async.cg.shared.global [%0], [%1], 16;" :: "r"(s), "l"(g) : "memory");
}
__device__ __forceinline__ void ldsm4(uint32_t* r, uint32_t addr) {
    asm volatile("ldmatrix.sync.aligned.m8n8.x4.shared.b16 {%0,%1,%2,%3}, [%4];"
                 : "=r"(r[0]), "=r"(r[1]), "=r"(r[2]), "=r"(r[3]) : "r"(addr));
}
__device__ __forceinline__ void mma16816(float* c, const uint32_t* a, const uint32_t* b) {
    asm volatile(
        "mma.sync.aligned.m16n8k16.row.col.f32.bf16.bf16.f32 "
        "{%0,%1,%2,%3}, {%4,%5,%6,%7}, {%8,%9}, {%0,%1,%2,%3};"
        : "+f"(c[0]), "+f"(c[1]), "+f"(c[2]), "+f"(c[3])
        : "r"(a[0]), "r"(a[1]), "r"(a[2]), "r"(a[3]), "r"(b[0]), "r"(b[1]));
}
__device__ __forceinline__ float gelu_exact(float v) {
    return 0.5f * v * (1.0f + erff(v * 0.70710678118654752440f));
}
__device__ __forceinline__ void split_bf16(float v, bf16& h, bf16& l) {
    h = __float2bfloat16(v);
    l = __float2bfloat16(v - __bfloat162float(h));
}

// ---------------- mask + last_idx ----------------
__global__ void mask_kernel(const int* __restrict__ cards,
                            char* __restrict__ mask, int* __restrict__ lastidx) {
    int b = blockIdx.x;
    int t = threadIdx.x;
    bool valid = cards[b * T_ + t] != 0;
    bool any = __syncthreads_or(valid);
    bool m = valid || (t == 0 && !any);
    mask[b * T_ + t] = m ? 1 : 0;
    int cnt = __syncthreads_count(m);
    if (t == 0) lastidx[b] = (cnt - 1) > 0 ? (cnt - 1) : 0;
}

// ---------------- deck means ----------------
__global__ void deckmean_kernel(const int* __restrict__ deck, const int* __restrict__ opp,
                                const float* __restrict__ tok, float* __restrict__ dm) {
    int b = blockIdx.x;
    int d = threadIdx.x;
    float s = 0.f;
    #pragma unroll
    for (int i = 0; i < 8; i++) {
        s += tok[(size_t)deck[b * 8 + i] * D_ + d];
        s += tok[(size_t)opp [b * 8 + i] * D_ + d];
    }
    dm[b * D_ + d] = s * 0.125f;
}

// ---------------- embedding sum ----------------
__global__ void embed_kernel(const int* __restrict__ cards, const int* __restrict__ players,
                             const float* __restrict__ tok, const float* __restrict__ pemb,
                             const float* __restrict__ pos, const float* __restrict__ dm,
                             float* __restrict__ x) {
    int bt = blockIdx.x;
    int b = bt >> 9;
    int t = bt & 511;
    int card = cards[bt];
    int pl = players[bt]; pl = pl < 0 ? 0 : (pl > 1 ? 1 : pl);
    const float* tr = tok  + (size_t)card * D_;
    const float* pr = pemb + (size_t)pl * D_;
    const float* qr = pos  + (size_t)t * D_;
    const float* mr = dm   + (size_t)b * D_;
    float* xr = x + (size_t)bt * D_;
    for (int d = threadIdx.x; d < D_; d += 256)
        xr[d] = tr[d] + pr[d] + mr[d] + qr[d];
}

// ---------------- layernorm -> bf16 hi/lo (or fp32 for final) ----------------
template<bool TOBF>
__global__ void ln_kernel(const float* __restrict__ x, const float* __restrict__ g,
                          const float* __restrict__ be, float* __restrict__ of,
                          bf16* __restrict__ oh, bf16* __restrict__ ol) {
    __shared__ float sh1[8], sh2[8];
    int r = blockIdx.x;
    size_t base = (size_t)r * D_;
    int t = threadIdx.x;
    float v0 = x[base + t], v1 = x[base + t + 256], v2 = x[base + t + 512];
    float s = v0 + v1 + v2;
    float q = v0 * v0 + v1 * v1 + v2 * v2;
    #pragma unroll
    for (int o2 = 16; o2; o2 >>= 1) {
        s += __shfl_xor_sync(0xffffffffu, s, o2);
        q += __shfl_xor_sync(0xffffffffu, q, o2);
    }
    if ((t & 31) == 0) { sh1[t >> 5] = s; sh2[t >> 5] = q; }
    __syncthreads();
    s = sh1[t & 7]; q = sh2[t & 7];
    #pragma unroll
    for (int o2 = 4; o2; o2 >>= 1) {
        s += __shfl_xor_sync(0xffffffffu, s, o2);
        q += __shfl_xor_sync(0xffffffffu, q, o2);
    }
    float mean = s * (1.0f / D_);
    float var  = q * (1.0f / D_) - mean * mean;
    float rstd = rsqrtf(var + 1e-5f);
    #pragma unroll
    for (int u = 0; u < 3; u++) {
        int d = t + u * 256;
        float v = (u == 0 ? v0 : (u == 1 ? v1 : v2));
        float o = (v - mean) * rstd * g[d] + be[d];
        if (TOBF) {
            bf16 hi, lo; split_bf16(o, hi, lo);
            oh[base + d] = hi; ol[base + d] = lo;
        } else {
            of[base + d] = o;
        }
    }
}

// ---------------- weight transpose + bf16 split: W[K,N] -> T[N,K] hi/lo ----------------
__global__ void transpose_split(const float* __restrict__ W, bf16* __restrict__ Th,
                                bf16* __restrict__ Tl, int K, int N) {
    __shared__ float tile[32][33];
    int n0 = blockIdx.x * 32, k0 = blockIdx.y * 32;
    int tx = threadIdx.x, ty = threadIdx.y;   // 32x8
    #pragma unroll
    for (int i = 0; i < 32; i += 8)
        tile[ty + i][tx] = W[(size_t)(k0 + ty + i) * N + n0 + tx];
    __syncthreads();
    #pragma unroll
    for (int i = 0; i < 32; i += 8) {
        float v = tile[tx][ty + i];
        bf16 h, l; split_bf16(v, h, l);
        size_t o = (size_t)(n0 + ty + i) * K + k0 + tx;
        Th[o] = h; Tl[o] = l;
    }
}

// ---------------- mma.sync bf16x3 GEMM ----------------
// C[M,N] = epi( (Ah+Al)[M,K] @ (Bh+Bl)[N,K]^T + bias )
// Tile: BM=128, BN=256, BK=32. 256 threads = 8 warps (2 in M x 4 in N), each 64x64.
// Products: Ah*Bh + Ah*Bl + Al*Bh (bf16x3). fp32 accumulate via HMMA.
// smem rows padded to 80B stride -> ldmatrix conflict-free.
// EPI: 0 = bias -> fp32; 1 = bias+gelu -> bf16 hi/lo; 2 = bias+residual -> fp32
#define ROWB 80
#define A_HI_OFF 0
#define A_LO_OFF (128 * ROWB)              // 10240
#define B_HI_OFF (2 * 128 * ROWB)          // 20480
#define B_LO_OFF (B_HI_OFF + 256 * ROWB)   // 40960
#define STAGE_BYTES (B_LO_OFF + 256 * ROWB) // 61440
#define GEMM_SMEM (2 * STAGE_BYTES)         // 122880

template<int EPI>
__global__ __launch_bounds__(256, 1)
void gemm_mma(const bf16* __restrict__ Ah, const bf16* __restrict__ Al,
              const bf16* __restrict__ Bh, const bf16* __restrict__ Bl,
              const float* __restrict__ bias, const float* __restrict__ res,
              float* __restrict__ outf, bf16* __restrict__ outh, bf16* __restrict__ outl,
              int K, int Nfull) {
    extern __shared__ char dsm[];
    uint32_t tiles = smem_u32(dsm);

    int tid = threadIdx.x;
    int wid = tid >> 5;
    int lane = tid & 31;
    int warp_m = wid & 1;        // 2 warps in M (64 rows each)
    int warp_n = wid >> 1;       // 4 warps in N (64 cols each)
    int m0 = blockIdx.y * 128;
    int n0 = blockIdx.x * 256;
    int nt = K >> 5;

    // ldmatrix per-lane offsets
    int aRow  = lane & 15;
    int aColB = (lane >> 4) << 4;                       // 0 or 16 bytes (k +8 elems)
    int bRow  = (lane & 7) + ((lane & 16) >> 1);        // 0..15
    int bColB = (lane & 8) << 1;                        // 0 or 16 bytes

    float acc[4][8][4];
    #pragma unroll
    for (int mt = 0; mt < 4; mt++)
        #pragma unroll
        for (int ntl = 0; ntl < 8; ntl++)
            #pragma unroll
            for (int r = 0; r < 4; r++) acc[mt][ntl][r] = 0.f;

    // -------- stage loader (cp.async) --------
    auto load_stage = [&](int kt, int st) {
        uint32_t sb = tiles + st * STAGE_BYTES;
        int k0 = kt << 5;
        #pragma unroll
        for (int i = 0; i < 2; i++) {                    // A: 128 rows x 4 chunks
            int id = tid + (i << 8);
            int r = id >> 2, c = id & 3;
            size_t go = (size_t)(m0 + r) * K + k0 + (c << 3);
            uint32_t so = r * ROWB + (c << 4);
            cp16(sb + A_HI_OFF + so, Ah + go);
            cp16(sb + A_LO_OFF + so, Al + go);
        }
        #pragma unroll
        for (int i = 0; i < 4; i++) {                    // B: 256 rows x 4 chunks
            int id = tid + (i << 8);
            int r = id >> 2, c = id & 3;
            size_t go = (size_t)(n0 + r) * K + k0 + (c << 3);
            uint32_t so = r * ROWB + (c << 4);
            cp16(sb + B_HI_OFF + so, Bh + go);
            cp16(sb + B_LO_OFF + so, Bl + go);
        }
        asm volatile("cp.async.commit_group;" ::: "memory");
    };

    load_stage(0, 0);

    uint32_t aFrag[16], bH[16], bL[16];

    for (int kt = 0; kt < nt; kt++) {
        int cur = kt & 1;
        if (kt + 1 < nt) {
            load_stage(kt + 1, cur ^ 1);
            asm volatile("cp.async.wait_group 1;" ::: "memory");
        } else {
            asm volatile("cp.async.wait_group 0;" ::: "memory");
        }
        __syncthreads();

        uint32_t sb = tiles + cur * STAGE_BYTES;
        uint32_t aBase = sb + (warp_m * 64 + aRow) * ROWB + aColB;
        uint32_t bBase = sb + B_HI_OFF + (warp_n * 64 + bRow) * ROWB + bColB;

        #pragma unroll
        for (int ks = 0; ks < 2; ks++) {
            uint32_t kb = ks << 5;                      // 16 elems = 32 bytes
            // A_hi fragments (4 m-tiles)
            #pragma unroll
            for (int mt = 0; mt < 4; mt++)
                ldsm4(&aFrag[4 * mt], aBase + A_HI_OFF + mt * (16 * ROWB) + kb);
            // B_hi + B_lo fragments (8 n-tiles = 4 x4 loads each)
            #pragma unroll
            for (int p = 0; p < 4; p++) {
                ldsm4(&bH[4 * p], bBase + p * (16 * ROWB) + kb);
                ldsm4(&bL[4 * p], bBase + (B_LO_OFF - B_HI_OFF) + p * (16 * ROWB) + kb);
            }
            // Ah*Bh and Ah*Bl
            #pragma unroll
            for (int mt = 0; mt < 4; mt++)
                #pragma unroll
                for (int ntl = 0; ntl < 8; ntl++) {
                    mma16816(acc[mt][ntl], &aFrag[4 * mt], &bH[2 * ntl]);
                    mma16816(acc[mt][ntl], &aFrag[4 * mt], &bL[2 * ntl]);
                }
            // A_lo fragments, then Al*Bh
            #pragma unroll
            for (int mt = 0; mt < 4; mt++)
                ldsm4(&aFrag[4 * mt], aBase + A_LO_OFF + mt * (16 * ROWB) + kb);
            #pragma unroll
            for (int mt = 0; mt < 4; mt++)
                #pragma unroll
                for (int ntl = 0; ntl < 8; ntl++)
                    mma16816(acc[mt][ntl], &aFrag[4 * mt], &bH[2 * ntl]);
        }
        __syncthreads();
    }

    // -------- epilogue --------
    int m_base = m0 + warp_m * 64 + (lane >> 2);
    int n_base = n0 + warp_n * 64 + ((lane & 3) << 1);
    #pragma unroll
    for (int mt = 0; mt < 4; mt++) {
        #pragma unroll
        for (int ntl = 0; ntl < 8; ntl++) {
            int n = n_base + ntl * 8;
            float b0 = bias[n], b1 = bias[n + 1];
            #pragma unroll
            for (int rr = 0; rr < 2; rr++) {
                int m = m_base + mt * 16 + rr * 8;
                size_t ob = (size_t)m * Nfull + n;
                float v0 = acc[mt][ntl][2 * rr]     + b0;
                float v1 = acc[mt][ntl][2 * rr + 1] + b1;
                if (EPI == 0) {
                    *(float2*)(outf + ob) = make_float2(v0, v1);
                } else if (EPI == 2) {
                    float2 rv = *(const float2*)(res + ob);
                    *(float2*)(outf + ob) = make_float2(v0 + rv.x, v1 + rv.y);
                } else {
                    float g0 = gelu_exact(v0), g1 = gelu_exact(v1);
                    bf16 h0, l0, h1, l1;
                    split_bf16(g0, h0, l0); split_bf16(g1, h1, l1);
                    __nv_bfloat162 ph; ph.x = h0; ph.y = h1;
                    __nv_bfloat162 pl; pl.x = l0; pl.y = l1;
                    *(__nv_bfloat162*)(outh + ob) = ph;
                    *(__nv_bfloat162*)(outl + ob) = pl;
                }
            }
        }
    }
}

// ---------------- flash attention (fp32), 64 q x 32 k tiles ----------------
__global__ __launch_bounds__(256)
void attn_kernel(const float* __restrict__ qkv, const char* __restrict__ mask,
                 bf16* __restrict__ outh, bf16* __restrict__ outl) {
    int qt = blockIdx.x, h = blockIdx.y, b = blockIdx.z;
    __shared__ float Qs[64][64];
    __shared__ float Kst[64][32];
    __shared__ float Vs[32][64];
    __shared__ float Ps[64][32];
    __shared__ char  Ms[32];

    int tid = threadIdx.x;
    int i = tid >> 2;
    int jq = tid & 3;
    int c0 = jq * 16;
    int gq = qt * 64 + i;
    const float scale = 0.125f;

    {
        int idx = tid * 16;
        int row = idx >> 6;
        int cc = idx & 63;
        const float* g = qkv + ((size_t)(b * T_ + qt * 64 + row)) * D3_ + h * DH_ + cc;
        #pragma unroll
        for (int u = 0; u < 4; u++)
            *(float4*)&Qs[row][cc + u * 4] = *(const float4*)(g + u * 4);
    }

    float O[16];
    #pragma unroll
    for (int cc = 0; cc < 16; cc++) O[cc] = 0.f;
    float m_prev = -INFINITY, l = 0.f;

    int ktmax = (qt + 1) * 2;
    for (int kt = 0; kt < ktmax; kt++) {
        __syncthreads();
        {
            int j = tid >> 3;
            int d0 = (tid & 7) * 8;
            const float* gk = qkv + ((size_t)(b * T_ + kt * 32 + j)) * D3_ + D_ + h * DH_ + d0;
            const float* gv = qkv + ((size_t)(b * T_ + kt * 32 + j)) * D3_ + 2 * D_ + h * DH_ + d0;
            float4 k0v = *(const float4*)gk;
            float4 k1v = *(const float4*)(gk + 4);
            Kst[d0 + 0][j] = k0v.x; Kst[d0 + 1][j] = k0v.y;
            Kst[d0 + 2][j] = k0v.z; Kst[d0 + 3][j] = k0v.w;
            Kst[d0 + 4][j] = k1v.x; Kst[d0 + 5][j] = k1v.y;
            Kst[d0 + 6][j] = k1v.z; Kst[d0 + 7][j] = k1v.w;
            *(float4*)&Vs[j][d0]     = *(const float4*)gv;
            *(float4*)&Vs[j][d0 + 4] = *(const float4*)(gv + 4);
            if (tid < 32) Ms[tid] = mask[b * T_ + kt * 32 + tid];
        }
        __syncthreads();

        float s[8];
        #pragma unroll
        for (int jj = 0; jj < 8; jj++) s[jj] = 0.f;
        #pragma unroll
        for (int k = 0; k < 64; k++) {
            float qv = Qs[i][k];
            float4 ka = *(const float4*)&Kst[k][jq * 8];
            float4 kb = *(const float4*)&Kst[k][jq * 8 + 4];
            s[0] += qv * ka.x; s[1] += qv * ka.y; s[2] += qv * ka.z; s[3] += qv * ka.w;
            s[4] += qv * kb.x; s[5] += qv * kb.y; s[6] += qv * kb.z; s[7] += qv * kb.w;
        }
        float mt = -INFINITY;
        #pragma unroll
        for (int jj = 0; jj < 8; jj++) {
            int gk = kt * 32 + jq * 8 + jj;
            bool ok = (gk <= gq) && (Ms[jq * 8 + jj] != 0);
            s[jj] = ok ? s[jj] * scale : -INFINITY;
            mt = fmaxf(mt, s[jj]);
        }
        mt = fmaxf(mt, __shfl_xor_sync(0xffffffffu, mt, 1));
        mt = fmaxf(mt, __shfl_xor_sync(0xffffffffu, mt, 2));
        float m_new = fmaxf(m_prev, mt);
        float alpha, psum = 0.f;
        float p[8];
        if (m_new == -INFINITY) {
            alpha = 1.0f;
            #pragma unroll
            for (int jj = 0; jj < 8; jj++) p[jj] = 0.f;
        } else {
            alpha = expf(m_prev - m_new);
            #pragma unroll
            for (int jj = 0; jj < 8; jj++) {
                p[jj] = expf(s[jj] - m_new);
                psum += p[jj];
            }
        }
        psum += __shfl_xor_sync(0xffffffffu, psum, 1);
        psum += __shfl_xor_sync(0xffffffffu, psum, 2);
        l = l * alpha + psum;
        m_prev = m_new;
        #pragma unroll
        for (int cc = 0; cc < 16; cc++) O[cc] *= alpha;
        #pragma unroll
        for (int jj = 0; jj < 8; jj++) Ps[i][jq * 8 + jj] = p[jj];
        __syncthreads();

        #pragma unroll 8
        for (int j = 0; j < 32; j++) {
            float pv = Ps[i][j];
            float4 v0 = *(const float4*)&Vs[j][c0];
            float4 v1 = *(const float4*)&Vs[j][c0 + 4];
            float4 v2 = *(const float4*)&Vs[j][c0 + 8];
            float4 v3 = *(const float4*)&Vs[j][c0 + 12];
            O[0]  += pv * v0.x; O[1]  += pv * v0.y; O[2]  += pv * v0.z; O[3]  += pv * v0.w;
            O[4]  += pv * v1.x; O[5]  += pv * v1.y; O[6]  += pv * v1.z; O[7]  += pv * v1.w;
            O[8]  += pv * v2.x; O[9]  += pv * v2.y; O[10] += pv * v2.z; O[11] += pv * v2.w;
            O[12] += pv * v3.x; O[13] += pv * v3.y; O[14] += pv * v3.z; O[15] += pv * v3.w;
        }
    }

    float rl = (l > 0.f) ? (1.0f / l) : 0.f;
    size_t ob = ((size_t)(b * T_ + qt * 64 + i)) * D_ + h * DH_ + c0;
    #pragma unroll
    for (int cc = 0; cc < 16; cc++) {
        float v = O[cc] * rl;
        bf16 hi, lo; split_bf16(v, hi, lo);
        outh[ob + cc] = hi; outl[ob + cc] = lo;
    }
}

// ---------------- head ----------------
__global__ void head_kernel(const float* __restrict__ xn, const int* __restrict__ lastidx,
                            const float* __restrict__ hw, const float* __restrict__ hb,
                            float* __restrict__ out) {
    int b = blockIdx.x;
    int w = threadIdx.x >> 5;
    int lane = threadIdx.x & 31;
    const float* h = xn + ((size_t)(b * T_ + lastidx[b])) * D_;
    float s = 0.f;
    for (int d = lane; d < D_; d += 32) s += h[d] * hw[d * 9 + w];
    #pragma unroll
    for (int o = 16; o; o >>= 1) s += __shfl_down_sync(0xffffffffu, s, o);
    if (lane == 0) out[b * 9 + w] = s + hb[w];
}

// ---------------- orchestration ----------------
extern "C" void kernel_launch(void* const* d_in, const int* in_sizes, int n_in,
                              void* d_out, int out_size) {
    const int*   cards   = (const int*)  d_in[0];
    const int*   players = (const int*)  d_in[1];
    const int*   deck    = (const int*)  d_in[2];
    const int*   opp     = (const int*)  d_in[3];
    const float* tok     = (const float*)d_in[4];
    const float* pemb    = (const float*)d_in[5];
    const float* pos     = (const float*)d_in[6];
    const float* ln1s = (const float*)d_in[9];
    const float* ln1b = (const float*)d_in[10];
    const float* qkvw = (const float*)d_in[11];
    const float* qkvb = (const float*)d_in[12];
    const float* projw = (const float*)d_in[13];
    const float* projb = (const float*)d_in[14];
    const float* ln2s = (const float*)d_in[15];
    const float* ln2b = (const float*)d_in[16];
    const float* fc1w = (const float*)d_in[17];
    const float* fc1b = (const float*)d_in[18];
    const float* fc2w = (const float*)d_in[19];
    const float* fc2b = (const float*)d_in[20];
    const float* lnfs = (const float*)d_in[21];
    const float* lnfb = (const float*)d_in[22];
    const float* headw = (const float*)d_in[23];
    const float* headb = (const float*)d_in[24];

    float *x, *xn, *qkv, *dm;
    bf16 *xh, *xl, *yh, *yl, *hh, *hl;
    bf16 *qT_h, *qT_l, *pT_h, *pT_l, *f1T_h, *f1T_l, *f2T_h, *f2T_l;
    char* mask; int* lastidx;
    cudaGetSymbolAddress((void**)&x,    g_x);
    cudaGetSymbolAddress((void**)&xn,   g_xn);
    cudaGetSymbolAddress((void**)&qkv,  g_qkv);
    cudaGetSymbolAddress((void**)&dm,   g_dm);
    cudaGetSymbolAddress((void**)&xh,   g_xh);
    cudaGetSymbolAddress((void**)&xl,   g_xl);
    cudaGetSymbolAddress((void**)&yh,   g_yh);
    cudaGetSymbolAddress((void**)&yl,   g_yl);
    cudaGetSymbolAddress((void**)&hh,   g_hh);
    cudaGetSymbolAddress((void**)&hl,   g_hl);
    cudaGetSymbolAddress((void**)&qT_h, g_qkvT_h);
    cudaGetSymbolAddress((void**)&qT_l, g_qkvT_l);
    cudaGetSymbolAddress((void**)&pT_h, g_projT_h);
    cudaGetSymbolAddress((void**)&pT_l, g_projT_l);
    cudaGetSymbolAddress((void**)&f1T_h, g_fc1T_h);
    cudaGetSymbolAddress((void**)&f1T_l, g_fc1T_l);
    cudaGetSymbolAddress((void**)&f2T_h, g_fc2T_h);
    cudaGetSymbolAddress((void**)&f2T_l, g_fc2T_l);
    cudaGetSymbolAddress((void**)&mask, g_mask);
    cudaGetSymbolAddress((void**)&lastidx, g_lastidx);

    cudaFuncSetAttribute(gemm_mma<0>, cudaFuncAttributeMaxDynamicSharedMemorySize, GEMM_SMEM);
    cudaFuncSetAttribute(gemm_mma<1>, cudaFuncAttributeMaxDynamicSharedMemorySize, GEMM_SMEM);
    cudaFuncSetAttribute(gemm_mma<2>, cudaFuncAttributeMaxDynamicSharedMemorySize, GEMM_SMEM);

    mask_kernel<<<B_, T_>>>(cards, mask, lastidx);
    deckmean_kernel<<<B_, D_>>>(deck, opp, tok, dm);
    embed_kernel<<<BT_, 256>>>(cards, players, tok, pemb, pos, dm, x);

    dim3 tb(32, 8);
    for (int i = 0; i < L_; i++) {
        transpose_split<<<dim3(D3_ / 32, D_ / 32), tb>>>(
            qkvw + (size_t)i * D_ * D3_, qT_h + (size_t)i * D3_ * D_, qT_l + (size_t)i * D3_ * D_, D_, D3_);
        transpose_split<<<dim3(D_ / 32, D_ / 32), tb>>>(
            projw + (size_t)i * D_ * D_, pT_h + (size_t)i * D_ * D_, pT_l + (size_t)i * D_ * D_, D_, D_);
        transpose_split<<<dim3(D4_ / 32, D_ / 32), tb>>>(
            fc1w + (size_t)i * D_ * D4_, f1T_h + (size_t)i * D4_ * D_, f1T_l + (size_t)i * D4_ * D_, D_, D4_);
        transpose_split<<<dim3(D_ / 32, D4_ / 32), tb>>>(
            fc2w + (size_t)i * D4_ * D_, f2T_h + (size_t)i * D_ * D4_, f2T_l + (size_t)i * D_ * D4_, D4_, D_);
    }

    for (int i = 0; i < L_; i++) {
        ln_kernel<true><<<BT_, 256>>>(x, ln1s + i * D_, ln1b + i * D_, nullptr, xh, xl);
        gemm_mma<0><<<dim3(D3_ / 256, BT_ / 128), 256, GEMM_SMEM>>>(
            xh, xl, qT_h + (size_t)i * D3_ * D_, qT_l + (size_t)i * D3_ * D_,
            qkvb + i * D3_, nullptr, qkv, nullptr, nullptr, D_, D3_);
        attn_kernel<<<dim3(T_ / 64, NH_, B_), 256>>>(qkv, mask, yh, yl);
        gemm_mma<2><<<dim3(D_ / 256, BT_ / 128), 256, GEMM_SMEM>>>(
            yh, yl, pT_h + (size_t)i * D_ * D_, pT_l + (size_t)i * D_ * D_,
            projb + i * D_, x, x, nullptr, nullptr, D_, D_);
        ln_kernel<true><<<BT_, 256>>>(x, ln2s + i * D_, ln2b + i * D_, nullptr, xh, xl);
        gemm_mma<1><<<dim3(D4_ / 256, BT_ / 128), 256, GEMM_SMEM>>>(
            xh, xl, f1T_h + (size_t)i * D4_ * D_, f1T_l + (size_t)i * D4_ * D_,
            fc1b + i * D4_, nullptr, nullptr, hh, hl, D_, D4_);
        gemm_mma<2><<<dim3(D_ / 256, BT_ / 128), 256, GEMM_SMEM>>>(
            hh, hl, f2T_h + (size_t)i * D_ * D4_, f2T_l + (size_t)i * D_ * D4_,
            fc2b + i * D_, x, x, nullptr, nullptr, D4_, D_);
    }

    ln_kernel<false><<<BT_, 256>>>(x, lnfs, lnfb, xn, nullptr, nullptr);
    head_kernel<<<B_, 288>>>(xn, lastidx, headw, headb, (float*)d_out);
}